// round 1
// baseline (speedup 1.0000x reference)
#include <cuda_runtime.h>

#define NN 50000
#define EE 640000
#define CC 128

// ---------------- device scratch (no allocations allowed) ----------------
__device__ float    g_hsrc[NN * CC];   // h_src = in @ Ws
__device__ float    g_skip[NN * CC];   // skip  = in @ Wl
__device__ float    g_agg [NN * CC];   // attention-weighted aggregation
__device__ float    g_h   [NN * CC];   // layer-1 output
__device__ float    g_as  [NN];        // alpha_src per node
__device__ float    g_ad  [NN];        // alpha_dst per node
__device__ unsigned g_emax[NN];        // segment max (monotonic uint encoding)
__device__ float    g_esum[NN];        // segment sum of exp
__device__ float    g_e   [EE];        // per-edge logit -> exp
__device__ float    g_was1[CC], g_wad1[CC], g_was2[CC], g_wad2[CC]; // W@a combos

// monotonic float->uint map (total order preserved)
__device__ __forceinline__ unsigned f2u_mono(float f) {
    unsigned u = __float_as_uint(f);
    return (u & 0x80000000u) ? ~u : (u | 0x80000000u);
}
__device__ __forceinline__ float u2f_mono(unsigned u) {
    return (u & 0x80000000u) ? __uint_as_float(u & 0x7FFFFFFFu)
                             : __uint_as_float(~u);
}

// ---------------- tiny: w = W @ a for both layers (4 vectors) ----------------
__global__ void combo_kernel(const float* __restrict__ W1s, const float* __restrict__ a1s,
                             const float* __restrict__ W1d, const float* __restrict__ a1d,
                             const float* __restrict__ W2s, const float* __restrict__ a2s,
                             const float* __restrict__ W2d, const float* __restrict__ a2d) {
    int k = threadIdx.x;  // 128 threads
    float s1 = 0.f, d1 = 0.f, s2 = 0.f, d2 = 0.f;
    #pragma unroll 8
    for (int c = 0; c < CC; c++) {
        s1 += W1s[k * CC + c] * a1s[c];
        d1 += W1d[k * CC + c] * a1d[c];
        s2 += W2s[k * CC + c] * a2s[c];
        d2 += W2d[k * CC + c] * a2d[c];
    }
    g_was1[k] = s1; g_wad1[k] = d1; g_was2[k] = s2; g_wad2[k] = d2;
}

// ---------------- init agg/emax/esum ----------------
__global__ void init_kernel(int M) {
    int i = blockIdx.x * blockDim.x + threadIdx.x;
    if (i < M * CC) g_agg[i] = 0.f;
    if (i < M) { g_emax[i] = 0x007FFFFFu; /* encoded -inf */ g_esum[i] = 0.f; }
}

// ---------------- SGEMM: C0 = A @ B0 -> g_hsrc ; C1 = A @ B1 -> g_skip ----------------
// M x 128 @ 128 x 128, block tile 128x128, BK=8, 256 threads, 8x8 per thread.
__global__ __launch_bounds__(256) void sgemm_kernel(const float* __restrict__ A,
                                                    const float* __restrict__ B0,
                                                    const float* __restrict__ B1,
                                                    int M) {
    const float* B    = (blockIdx.y == 0) ? B0 : B1;
    float*       Cout = (blockIdx.y == 0) ? g_hsrc : g_skip;

    __shared__ float As[8][128];
    __shared__ float Bs[8][128];

    const int tid = threadIdx.x;
    const int tx = tid & 15;       // 0..15 -> 8 output cols each
    const int ty = tid >> 4;       // 0..15 -> 8 output rows each
    const int row0 = blockIdx.x * 128;

    const int lr = tid >> 1;           // A tile row 0..127
    const int lc = (tid & 1) * 4;      // A tile col 0 or 4
    const int bk = tid >> 5;           // B tile row 0..7
    const int bn = (tid & 31) * 4;     // B tile col

    float acc[8][8];
    #pragma unroll
    for (int i = 0; i < 8; i++)
        #pragma unroll
        for (int j = 0; j < 8; j++) acc[i][j] = 0.f;

    for (int k0 = 0; k0 < 128; k0 += 8) {
        float4 av = make_float4(0.f, 0.f, 0.f, 0.f);
        int gr = row0 + lr;
        if (gr < M) av = *(const float4*)(A + gr * 128 + k0 + lc);
        As[lc + 0][lr] = av.x; As[lc + 1][lr] = av.y;
        As[lc + 2][lr] = av.z; As[lc + 3][lr] = av.w;

        *(float4*)&Bs[bk][bn] = *(const float4*)(B + (k0 + bk) * 128 + bn);
        __syncthreads();

        #pragma unroll
        for (int k = 0; k < 8; k++) {
            float rm[8], rn[8];
            #pragma unroll
            for (int i = 0; i < 8; i++) rm[i] = As[k][ty * 8 + i];
            #pragma unroll
            for (int j = 0; j < 8; j++) rn[j] = Bs[k][tx * 8 + j];
            #pragma unroll
            for (int i = 0; i < 8; i++)
                #pragma unroll
                for (int j = 0; j < 8; j++) acc[i][j] += rm[i] * rn[j];
        }
        __syncthreads();
    }

    #pragma unroll
    for (int i = 0; i < 8; i++) {
        int gr = row0 + ty * 8 + i;
        if (gr < M) {
            #pragma unroll
            for (int j = 0; j < 8; j += 4) {
                float4 v = make_float4(acc[i][j], acc[i][j + 1], acc[i][j + 2], acc[i][j + 3]);
                *(float4*)(Cout + gr * 128 + tx * 8 + j) = v;
            }
        }
    }
}

// ---------------- GEMV: alpha_src[n] = x[n]@was, alpha_dst[n] = x[n]@wad ----------------
__global__ __launch_bounds__(256) void gemv_kernel(const float* __restrict__ X, int layer, int M) {
    int gt = blockIdx.x * blockDim.x + threadIdx.x;
    int n = gt >> 5;
    int lane = threadIdx.x & 31;
    if (n >= M) return;
    const float* was = (layer == 1) ? g_was1 : g_was2;
    const float* wad = (layer == 1) ? g_wad1 : g_wad2;
    float4 xv = *(const float4*)(X + n * 128 + lane * 4);
    float4 ws = *(const float4*)(was + lane * 4);
    float4 wd = *(const float4*)(wad + lane * 4);
    float s = xv.x * ws.x + xv.y * ws.y + xv.z * ws.z + xv.w * ws.w;
    float d = xv.x * wd.x + xv.y * wd.y + xv.z * wd.z + xv.w * wd.w;
    #pragma unroll
    for (int o = 16; o; o >>= 1) {
        s += __shfl_xor_sync(0xFFFFFFFFu, s, o);
        d += __shfl_xor_sync(0xFFFFFFFFu, d, o);
    }
    if (lane == 0) { g_as[n] = s; g_ad[n] = d; }
}

// ---------------- edge pass A: logits + segment max ----------------
__global__ __launch_bounds__(256) void edgeA_kernel(const int* __restrict__ src,
                                                    const int* __restrict__ dst, int E) {
    int i = blockIdx.x * blockDim.x + threadIdx.x;
    if (i >= E) return;
    int s = src[i], d = dst[i];
    float v = g_as[s] + g_ad[d];
    v = v > 0.f ? v : 0.2f * v;  // LeakyReLU(0.2)
    g_e[i] = v;
    atomicMax(&g_emax[d], f2u_mono(v));
}

// ---------------- edge pass B: exp + segment sum ----------------
__global__ __launch_bounds__(256) void edgeB_kernel(const int* __restrict__ dst, int E) {
    int i = blockIdx.x * blockDim.x + threadIdx.x;
    if (i >= E) return;
    int d = dst[i];
    float m = u2f_mono(g_emax[d]);
    float ex = __expf(g_e[i] - m);
    g_e[i] = ex;
    atomicAdd(&g_esum[d], ex);
}

// ---------------- edge pass C: weighted gather + scatter-add (warp/edge) ----------------
__global__ __launch_bounds__(256) void edgeC_kernel(const int* __restrict__ src,
                                                    const int* __restrict__ dst, int E) {
    int gt = blockIdx.x * blockDim.x + threadIdx.x;
    int e = gt >> 5;
    int lane = threadIdx.x & 31;
    if (e >= E) return;
    int s = __ldg(src + e), d = __ldg(dst + e);
    float alpha = g_e[e] / (g_esum[d] + 1e-16f);
    float4 v = *(const float4*)(g_hsrc + s * 128 + lane * 4);
    float4 w = make_float4(v.x * alpha, v.y * alpha, v.z * alpha, v.w * alpha);
    float* p = g_agg + d * 128 + lane * 4;
    asm volatile("red.global.add.v4.f32 [%0], {%1,%2,%3,%4};"
                 :: "l"(p), "f"(w.x), "f"(w.y), "f"(w.z), "f"(w.w) : "memory");
}

// ---------------- finish: out = agg + b + skip + bl (+ReLU for layer 1) ----------------
__global__ __launch_bounds__(256) void finish_kernel(const float* __restrict__ b,
                                                     const float* __restrict__ bl,
                                                     float* __restrict__ out_ext,
                                                     int relu_to_gh, int M) {
    int i = blockIdx.x * blockDim.x + threadIdx.x;
    if (i >= M * CC) return;
    int c = i & 127;
    float v = g_agg[i] + b[c] + g_skip[i] + bl[c];
    if (relu_to_gh) g_h[i] = fmaxf(v, 0.f);
    else            out_ext[i] = v;
}

// ---------------- launch ----------------
extern "C" void kernel_launch(void* const* d_in, const int* in_sizes, int n_in,
                              void* d_out, int out_size) {
    const float* x   = (const float*)d_in[0];
    const int*   ei  = (const int*)  d_in[1];
    const float* W1s = (const float*)d_in[2];
    const float* W1d = (const float*)d_in[3];
    const float* a1s = (const float*)d_in[4];
    const float* a1d = (const float*)d_in[5];
    const float* b1  = (const float*)d_in[6];
    const float* Wl1 = (const float*)d_in[7];
    const float* bl1 = (const float*)d_in[8];
    const float* W2s = (const float*)d_in[9];
    const float* W2d = (const float*)d_in[10];
    const float* a2s = (const float*)d_in[11];
    const float* a2d = (const float*)d_in[12];
    const float* b2  = (const float*)d_in[13];
    const float* Wl2 = (const float*)d_in[14];
    const float* bl2 = (const float*)d_in[15];

    const int M = in_sizes[0] / CC;        // 50000
    const int E = in_sizes[1] / 2;         // 640000
    const int* src = ei;
    const int* dst = ei + E;

    float* p_h = nullptr;
    cudaGetSymbolAddress((void**)&p_h, g_h);  // query only, capture-safe

    const int nodeBlocks = (M * CC + 255) / 256;
    const int edgeBlocks = (E + 255) / 256;
    const int edgeWarpBlocks = (int)(((long long)E * 32 + 255) / 256);
    const int gemvBlocks = (int)(((long long)M * 32 + 255) / 256);
    const dim3 gemmGrid((M + 127) / 128, 2);

    combo_kernel<<<1, 128>>>(W1s, a1s, W1d, a1d, W2s, a2s, W2d, a2d);

    // ---- layer 1 ----
    init_kernel<<<nodeBlocks, 256>>>(M);
    sgemm_kernel<<<gemmGrid, 256>>>(x, W1s, Wl1, M);
    gemv_kernel<<<gemvBlocks, 256>>>(x, 1, M);
    edgeA_kernel<<<edgeBlocks, 256>>>(src, dst, E);
    edgeB_kernel<<<edgeBlocks, 256>>>(dst, E);
    edgeC_kernel<<<edgeWarpBlocks, 256>>>(src, dst, E);
    finish_kernel<<<nodeBlocks, 256>>>(b1, bl1, nullptr, 1, M);

    // ---- layer 2 ----
    init_kernel<<<nodeBlocks, 256>>>(M);
    sgemm_kernel<<<gemmGrid, 256>>>(p_h, W2s, Wl2, M);
    gemv_kernel<<<gemvBlocks, 256>>>(p_h, 2, M);
    edgeA_kernel<<<edgeBlocks, 256>>>(src, dst, E);
    edgeB_kernel<<<edgeBlocks, 256>>>(dst, E);
    edgeC_kernel<<<edgeWarpBlocks, 256>>>(src, dst, E);
    finish_kernel<<<nodeBlocks, 256>>>(b2, bl2, (float*)d_out, 0, M);
}

// round 2
// speedup vs baseline: 1.3692x; 1.3692x over previous
#include <cuda_runtime.h>
#include <cstdint>

#define NN 50000
#define EE 640000
#define CC 128

// ---------------- device scratch (no allocations allowed) ----------------
__device__ float    g_hsrc[NN * CC];   // h_src = in @ Ws
__device__ float    g_skip[NN * CC];   // skip  = in @ Wl
__device__ float    g_agg [NN * CC];   // attention-weighted aggregation
__device__ float    g_h   [NN * CC];   // layer-1 output
__device__ float    g_as  [NN];        // alpha_src per node
__device__ float    g_ad  [NN];        // alpha_dst per node
__device__ float    g_esum[NN];        // segment sum of exp
__device__ float    g_e   [EE];        // per-edge exp(logit)
__device__ float    g_was1[CC], g_wad1[CC], g_was2[CC], g_wad2[CC]; // W@a combos

// ---------------- tiny: w = W @ a for both layers (4 vectors) ----------------
__global__ void combo_kernel(const float* __restrict__ W1s, const float* __restrict__ a1s,
                             const float* __restrict__ W1d, const float* __restrict__ a1d,
                             const float* __restrict__ W2s, const float* __restrict__ a2s,
                             const float* __restrict__ W2d, const float* __restrict__ a2d) {
    int k = threadIdx.x;  // 128 threads
    float s1 = 0.f, d1 = 0.f, s2 = 0.f, d2 = 0.f;
    #pragma unroll 8
    for (int c = 0; c < CC; c++) {
        s1 += W1s[k * CC + c] * a1s[c];
        d1 += W1d[k * CC + c] * a1d[c];
        s2 += W2s[k * CC + c] * a2s[c];
        d2 += W2d[k * CC + c] * a2d[c];
    }
    g_was1[k] = s1; g_wad1[k] = d1; g_was2[k] = s2; g_wad2[k] = d2;
}

// ---------------- init agg/esum ----------------
__global__ void init_kernel(int M) {
    int i = blockIdx.x * blockDim.x + threadIdx.x;
    if (i < M * CC) g_agg[i] = 0.f;
    if (i < M) g_esum[i] = 0.f;
}

// ---------------- tf32 tensor-core SGEMM ----------------
// C0 = A @ B0 -> g_hsrc ; C1 = A @ B1 -> g_skip (blockIdx.y selects).
// CTA tile 128x128, full K=128 resident in smem (tf32), one sync, then
// 16 k-steps of mma.sync.m16n8k8. 8 warps, each computes a 64x32 warp tile.
#define AS_STRIDE 132   // (4r + tig) mod 32 conflict-free
#define BS_STRIDE 136   // (8t + grp) mod 32 conflict-free
#define SMEM_BYTES ((128 * AS_STRIDE + 128 * BS_STRIDE) * 4)

__device__ __forceinline__ uint32_t f2tf32(float f) {
    uint32_t r;
    asm("cvt.rna.tf32.f32 %0, %1;" : "=r"(r) : "f"(f));
    return r;
}

__global__ __launch_bounds__(256) void sgemm_tf32_kernel(const float* __restrict__ A,
                                                         const float* __restrict__ B0,
                                                         const float* __restrict__ B1,
                                                         int M) {
    extern __shared__ uint32_t sm[];
    uint32_t* As = sm;                       // [row][k], stride AS_STRIDE
    uint32_t* Bs = sm + 128 * AS_STRIDE;     // [k][n],  stride BS_STRIDE

    const float* B    = (blockIdx.y == 0) ? B0 : B1;
    float*       Cout = (blockIdx.y == 0) ? g_hsrc : g_skip;

    const int tid  = threadIdx.x;
    const int row0 = blockIdx.x * 128;

    // ---- load phase: A tile + B, fp32 -> tf32(RN) -> smem ----
    #pragma unroll
    for (int i = 0; i < 16; i++) {
        int idx = tid + 256 * i;          // float4 slot
        int row = idx >> 5;
        int c4  = (idx & 31) << 2;
        int gr  = row0 + row;
        float4 av = make_float4(0.f, 0.f, 0.f, 0.f);
        if (gr < M) av = *(const float4*)(A + gr * 128 + c4);
        uint32_t* p = As + row * AS_STRIDE + c4;
        p[0] = f2tf32(av.x); p[1] = f2tf32(av.y);
        p[2] = f2tf32(av.z); p[3] = f2tf32(av.w);

        float4 bv = *(const float4*)(B + row * 128 + c4);
        uint32_t* q = Bs + row * BS_STRIDE + c4;
        q[0] = f2tf32(bv.x); q[1] = f2tf32(bv.y);
        q[2] = f2tf32(bv.z); q[3] = f2tf32(bv.w);
    }
    __syncthreads();

    // ---- compute phase ----
    const int w      = tid >> 5;
    const int lane   = tid & 31;
    const int warp_m = w >> 2;            // 0..1
    const int warp_n = w & 3;             // 0..3
    const int wr0    = warp_m * 64;
    const int wn0    = warp_n * 32;
    const int grp    = lane >> 2;         // 0..7
    const int tig    = lane & 3;          // 0..3

    float acc[4][4][4];
    #pragma unroll
    for (int mt = 0; mt < 4; mt++)
        #pragma unroll
        for (int nt = 0; nt < 4; nt++)
            #pragma unroll
            for (int r = 0; r < 4; r++) acc[mt][nt][r] = 0.f;

    #pragma unroll
    for (int k0 = 0; k0 < 128; k0 += 8) {
        uint32_t a[4][4];
        #pragma unroll
        for (int mt = 0; mt < 4; mt++) {
            int r = wr0 + mt * 16 + grp;
            const uint32_t* p = As + r * AS_STRIDE + k0 + tig;
            a[mt][0] = p[0];
            a[mt][1] = p[8 * AS_STRIDE];
            a[mt][2] = p[4];
            a[mt][3] = p[8 * AS_STRIDE + 4];
        }
        uint32_t b[4][2];
        #pragma unroll
        for (int nt = 0; nt < 4; nt++) {
            int c = wn0 + nt * 8 + grp;
            const uint32_t* p = Bs + (k0 + tig) * BS_STRIDE + c;
            b[nt][0] = p[0];
            b[nt][1] = p[4 * BS_STRIDE];
        }
        #pragma unroll
        for (int mt = 0; mt < 4; mt++)
            #pragma unroll
            for (int nt = 0; nt < 4; nt++) {
                float* d = acc[mt][nt];
                asm volatile(
                    "mma.sync.aligned.m16n8k8.row.col.f32.tf32.tf32.f32 "
                    "{%0,%1,%2,%3}, {%4,%5,%6,%7}, {%8,%9}, {%0,%1,%2,%3};"
                    : "+f"(d[0]), "+f"(d[1]), "+f"(d[2]), "+f"(d[3])
                    : "r"(a[mt][0]), "r"(a[mt][1]), "r"(a[mt][2]), "r"(a[mt][3]),
                      "r"(b[nt][0]), "r"(b[nt][1]));
            }
    }

    // ---- epilogue ----
    #pragma unroll
    for (int mt = 0; mt < 4; mt++) {
        int r_lo = row0 + wr0 + mt * 16 + grp;
        int r_hi = r_lo + 8;
        #pragma unroll
        for (int nt = 0; nt < 4; nt++) {
            int col = wn0 + nt * 8 + tig * 2;
            if (r_lo < M)
                *(float2*)(Cout + r_lo * 128 + col) = make_float2(acc[mt][nt][0], acc[mt][nt][1]);
            if (r_hi < M)
                *(float2*)(Cout + r_hi * 128 + col) = make_float2(acc[mt][nt][2], acc[mt][nt][3]);
        }
    }
}

// ---------------- GEMV: alpha_src[n] = x[n]@was, alpha_dst[n] = x[n]@wad ----------------
__global__ __launch_bounds__(256) void gemv_kernel(const float* __restrict__ X, int layer, int M) {
    int gt = blockIdx.x * blockDim.x + threadIdx.x;
    int n = gt >> 5;
    int lane = threadIdx.x & 31;
    if (n >= M) return;
    const float* was = (layer == 1) ? g_was1 : g_was2;
    const float* wad = (layer == 1) ? g_wad1 : g_wad2;
    float4 xv = *(const float4*)(X + n * 128 + lane * 4);
    float4 ws = *(const float4*)(was + lane * 4);
    float4 wd = *(const float4*)(wad + lane * 4);
    float s = xv.x * ws.x + xv.y * ws.y + xv.z * ws.z + xv.w * ws.w;
    float d = xv.x * wd.x + xv.y * wd.y + xv.z * wd.z + xv.w * wd.w;
    #pragma unroll
    for (int o = 16; o; o >>= 1) {
        s += __shfl_xor_sync(0xFFFFFFFFu, s, o);
        d += __shfl_xor_sync(0xFFFFFFFFu, d, o);
    }
    if (lane == 0) { g_as[n] = s; g_ad[n] = d; }
}

// ---------------- merged edge pass: logit -> exp -> segment sum ----------------
// Softmax is shift-invariant and logits here are O(10), so exp cannot overflow
// fp32; the max-subtraction pass is dropped entirely.
__global__ __launch_bounds__(256) void edgeAB_kernel(const int* __restrict__ src,
                                                     const int* __restrict__ dst, int E) {
    int i = blockIdx.x * blockDim.x + threadIdx.x;
    if (i >= E) return;
    int s = src[i], d = dst[i];
    float v = g_as[s] + g_ad[d];
    v = v > 0.f ? v : 0.2f * v;  // LeakyReLU(0.2)
    float ex = __expf(v);
    g_e[i] = ex;
    atomicAdd(&g_esum[d], ex);
}

// ---------------- edge pass C: weighted gather + scatter-add (warp/edge) ----------------
__global__ __launch_bounds__(256) void edgeC_kernel(const int* __restrict__ src,
                                                    const int* __restrict__ dst, int E) {
    int gt = blockIdx.x * blockDim.x + threadIdx.x;
    int e = gt >> 5;
    int lane = threadIdx.x & 31;
    if (e >= E) return;
    int s = __ldg(src + e), d = __ldg(dst + e);
    float alpha = g_e[e] / (g_esum[d] + 1e-16f);
    float4 v = *(const float4*)(g_hsrc + s * 128 + lane * 4);
    float4 w = make_float4(v.x * alpha, v.y * alpha, v.z * alpha, v.w * alpha);
    float* p = g_agg + d * 128 + lane * 4;
    asm volatile("red.global.add.v4.f32 [%0], {%1,%2,%3,%4};"
                 :: "l"(p), "f"(w.x), "f"(w.y), "f"(w.z), "f"(w.w) : "memory");
}

// ---------------- finish: out = agg + b + skip + bl (+ReLU for layer 1) ----------------
__global__ __launch_bounds__(256) void finish_kernel(const float* __restrict__ b,
                                                     const float* __restrict__ bl,
                                                     float* __restrict__ out_ext,
                                                     int relu_to_gh, int M) {
    int i = blockIdx.x * blockDim.x + threadIdx.x;
    if (i >= M * CC) return;
    int c = i & 127;
    float v = g_agg[i] + b[c] + g_skip[i] + bl[c];
    if (relu_to_gh) g_h[i] = fmaxf(v, 0.f);
    else            out_ext[i] = v;
}

// ---------------- launch ----------------
extern "C" void kernel_launch(void* const* d_in, const int* in_sizes, int n_in,
                              void* d_out, int out_size) {
    const float* x   = (const float*)d_in[0];
    const int*   ei  = (const int*)  d_in[1];
    const float* W1s = (const float*)d_in[2];
    const float* W1d = (const float*)d_in[3];
    const float* a1s = (const float*)d_in[4];
    const float* a1d = (const float*)d_in[5];
    const float* b1  = (const float*)d_in[6];
    const float* Wl1 = (const float*)d_in[7];
    const float* bl1 = (const float*)d_in[8];
    const float* W2s = (const float*)d_in[9];
    const float* W2d = (const float*)d_in[10];
    const float* a2s = (const float*)d_in[11];
    const float* a2d = (const float*)d_in[12];
    const float* b2  = (const float*)d_in[13];
    const float* Wl2 = (const float*)d_in[14];
    const float* bl2 = (const float*)d_in[15];

    const int M = in_sizes[0] / CC;        // 50000
    const int E = in_sizes[1] / 2;         // 640000
    const int* src = ei;
    const int* dst = ei + E;

    float* p_h = nullptr;
    cudaGetSymbolAddress((void**)&p_h, g_h);  // query only, capture-safe

    static bool attr_set = false;
    if (!attr_set) {
        cudaFuncSetAttribute(sgemm_tf32_kernel,
                             cudaFuncAttributeMaxDynamicSharedMemorySize, SMEM_BYTES);
        attr_set = true;
    }

    const int nodeBlocks = (M * CC + 255) / 256;
    const int edgeBlocks = (E + 255) / 256;
    const int edgeWarpBlocks = (int)(((long long)E * 32 + 255) / 256);
    const int gemvBlocks = (int)(((long long)M * 32 + 255) / 256);
    const dim3 gemmGrid((M + 127) / 128, 2);

    combo_kernel<<<1, 128>>>(W1s, a1s, W1d, a1d, W2s, a2s, W2d, a2d);

    // ---- layer 1 ----
    init_kernel<<<nodeBlocks, 256>>>(M);
    sgemm_tf32_kernel<<<gemmGrid, 256, SMEM_BYTES>>>(x, W1s, Wl1, M);
    gemv_kernel<<<gemvBlocks, 256>>>(x, 1, M);
    edgeAB_kernel<<<edgeBlocks, 256>>>(src, dst, E);
    edgeC_kernel<<<edgeWarpBlocks, 256>>>(src, dst, E);
    finish_kernel<<<nodeBlocks, 256>>>(b1, bl1, nullptr, 1, M);

    // ---- layer 2 ----
    init_kernel<<<nodeBlocks, 256>>>(M);
    sgemm_tf32_kernel<<<gemmGrid, 256, SMEM_BYTES>>>(p_h, W2s, Wl2, M);
    gemv_kernel<<<gemvBlocks, 256>>>(p_h, 2, M);
    edgeAB_kernel<<<edgeBlocks, 256>>>(src, dst, E);
    edgeC_kernel<<<edgeWarpBlocks, 256>>>(src, dst, E);
    finish_kernel<<<nodeBlocks, 256>>>(b2, bl2, (float*)d_out, 0, M);
}

// round 3
// speedup vs baseline: 2.1560x; 1.5747x over previous
#include <cuda_runtime.h>
#include <cstdint>

#define NN 50000
#define EE 640000
#define CC 128
#define SCAN_B 512

// ---------------- device scratch (no allocations allowed) ----------------
__device__ float    g_hsrc[NN * CC];   // h_src = in @ Ws
__device__ float    g_skip[NN * CC];   // skip  = in @ Wl
__device__ float    g_h   [NN * CC];   // layer-1 output
__device__ float    g_as  [NN];        // alpha_src per node
__device__ float    g_ad  [NN];        // alpha_dst per node
__device__ float    g_was1[CC], g_wad1[CC], g_was2[CC], g_wad2[CC];
// CSR (built once per launch; shared by both layers)
__device__ int      g_deg [NN];
__device__ int      g_off [NN + 1];
__device__ int      g_cur [NN];
__device__ int      g_bsum[128];
__device__ int      g_esrc[EE];        // src ids sorted by dst

// ---------------- tiny: w = W @ a for both layers ----------------
__global__ void combo_kernel(const float* __restrict__ W1s, const float* __restrict__ a1s,
                             const float* __restrict__ W1d, const float* __restrict__ a1d,
                             const float* __restrict__ W2s, const float* __restrict__ a2s,
                             const float* __restrict__ W2d, const float* __restrict__ a2d) {
    int k = threadIdx.x;  // 128 threads
    float s1 = 0.f, d1 = 0.f, s2 = 0.f, d2 = 0.f;
    #pragma unroll 8
    for (int c = 0; c < CC; c++) {
        s1 += W1s[k * CC + c] * a1s[c];
        d1 += W1d[k * CC + c] * a1d[c];
        s2 += W2s[k * CC + c] * a2s[c];
        d2 += W2d[k * CC + c] * a2d[c];
    }
    g_was1[k] = s1; g_wad1[k] = d1; g_was2[k] = s2; g_wad2[k] = d2;
}

// ---------------- CSR build ----------------
__global__ void zero_deg_kernel(int M) {
    int i = blockIdx.x * blockDim.x + threadIdx.x;
    if (i < M) g_deg[i] = 0;
}
__global__ void hist_kernel(const int* __restrict__ dst, int E) {
    int e = blockIdx.x * blockDim.x + threadIdx.x;
    if (e < E) atomicAdd(&g_deg[dst[e]], 1);
}
__global__ __launch_bounds__(SCAN_B) void scan1_kernel(int M) {
    __shared__ int sm[SCAN_B];
    int i = blockIdx.x * SCAN_B + threadIdx.x;
    int v = (i < M) ? g_deg[i] : 0;
    sm[threadIdx.x] = v;
    __syncthreads();
    for (int o = 1; o < SCAN_B; o <<= 1) {
        int t = (threadIdx.x >= o) ? sm[threadIdx.x - o] : 0;
        __syncthreads();
        sm[threadIdx.x] += t;
        __syncthreads();
    }
    if (i < M) g_off[i] = sm[threadIdx.x] - v;          // local exclusive
    if (threadIdx.x == SCAN_B - 1) g_bsum[blockIdx.x] = sm[threadIdx.x];
}
__global__ __launch_bounds__(128) void scan2_kernel(int B) {
    __shared__ int sm[128];
    int v = (threadIdx.x < B) ? g_bsum[threadIdx.x] : 0;
    sm[threadIdx.x] = v;
    __syncthreads();
    for (int o = 1; o < 128; o <<= 1) {
        int t = (threadIdx.x >= o) ? sm[threadIdx.x - o] : 0;
        __syncthreads();
        sm[threadIdx.x] += t;
        __syncthreads();
    }
    if (threadIdx.x < B) g_bsum[threadIdx.x] = sm[threadIdx.x] - v;  // exclusive
}
__global__ void scan3_kernel(int M, int E) {
    int i = blockIdx.x * blockDim.x + threadIdx.x;
    if (i < M) {
        int o = g_off[i] + g_bsum[i / SCAN_B];
        g_off[i] = o;
        g_cur[i] = o;
    }
    if (i == 0) g_off[M] = E;
}
__global__ void scatter_kernel(const int* __restrict__ src, const int* __restrict__ dst, int E) {
    int e = blockIdx.x * blockDim.x + threadIdx.x;
    if (e >= E) return;
    int pos = atomicAdd(&g_cur[dst[e]], 1);
    g_esrc[pos] = src[e];
}

// ---------------- tf32 tensor-core SGEMM (as round 2) ----------------
#define AS_STRIDE 132
#define BS_STRIDE 136
#define SMEM_BYTES ((128 * AS_STRIDE + 128 * BS_STRIDE) * 4)

__device__ __forceinline__ uint32_t f2tf32(float f) {
    uint32_t r;
    asm("cvt.rna.tf32.f32 %0, %1;" : "=r"(r) : "f"(f));
    return r;
}

__global__ __launch_bounds__(256) void sgemm_tf32_kernel(const float* __restrict__ A,
                                                         const float* __restrict__ B0,
                                                         const float* __restrict__ B1,
                                                         int M) {
    extern __shared__ uint32_t sm[];
    uint32_t* As = sm;
    uint32_t* Bs = sm + 128 * AS_STRIDE;

    const float* B    = (blockIdx.y == 0) ? B0 : B1;
    float*       Cout = (blockIdx.y == 0) ? g_hsrc : g_skip;

    const int tid  = threadIdx.x;
    const int row0 = blockIdx.x * 128;

    #pragma unroll
    for (int i = 0; i < 16; i++) {
        int idx = tid + 256 * i;
        int row = idx >> 5;
        int c4  = (idx & 31) << 2;
        int gr  = row0 + row;
        float4 av = make_float4(0.f, 0.f, 0.f, 0.f);
        if (gr < M) av = *(const float4*)(A + gr * 128 + c4);
        uint32_t* p = As + row * AS_STRIDE + c4;
        p[0] = f2tf32(av.x); p[1] = f2tf32(av.y);
        p[2] = f2tf32(av.z); p[3] = f2tf32(av.w);

        float4 bv = *(const float4*)(B + row * 128 + c4);
        uint32_t* q = Bs + row * BS_STRIDE + c4;
        q[0] = f2tf32(bv.x); q[1] = f2tf32(bv.y);
        q[2] = f2tf32(bv.z); q[3] = f2tf32(bv.w);
    }
    __syncthreads();

    const int w      = tid >> 5;
    const int lane   = tid & 31;
    const int warp_m = w >> 2;
    const int warp_n = w & 3;
    const int wr0    = warp_m * 64;
    const int wn0    = warp_n * 32;
    const int grp    = lane >> 2;
    const int tig    = lane & 3;

    float acc[4][4][4];
    #pragma unroll
    for (int mt = 0; mt < 4; mt++)
        #pragma unroll
        for (int nt = 0; nt < 4; nt++)
            #pragma unroll
            for (int r = 0; r < 4; r++) acc[mt][nt][r] = 0.f;

    #pragma unroll
    for (int k0 = 0; k0 < 128; k0 += 8) {
        uint32_t a[4][4];
        #pragma unroll
        for (int mt = 0; mt < 4; mt++) {
            int r = wr0 + mt * 16 + grp;
            const uint32_t* p = As + r * AS_STRIDE + k0 + tig;
            a[mt][0] = p[0];
            a[mt][1] = p[8 * AS_STRIDE];
            a[mt][2] = p[4];
            a[mt][3] = p[8 * AS_STRIDE + 4];
        }
        uint32_t b[4][2];
        #pragma unroll
        for (int nt = 0; nt < 4; nt++) {
            int c = wn0 + nt * 8 + grp;
            const uint32_t* p = Bs + (k0 + tig) * BS_STRIDE + c;
            b[nt][0] = p[0];
            b[nt][1] = p[4 * BS_STRIDE];
        }
        #pragma unroll
        for (int mt = 0; mt < 4; mt++)
            #pragma unroll
            for (int nt = 0; nt < 4; nt++) {
                float* d = acc[mt][nt];
                asm volatile(
                    "mma.sync.aligned.m16n8k8.row.col.f32.tf32.tf32.f32 "
                    "{%0,%1,%2,%3}, {%4,%5,%6,%7}, {%8,%9}, {%0,%1,%2,%3};"
                    : "+f"(d[0]), "+f"(d[1]), "+f"(d[2]), "+f"(d[3])
                    : "r"(a[mt][0]), "r"(a[mt][1]), "r"(a[mt][2]), "r"(a[mt][3]),
                      "r"(b[nt][0]), "r"(b[nt][1]));
            }
    }

    #pragma unroll
    for (int mt = 0; mt < 4; mt++) {
        int r_lo = row0 + wr0 + mt * 16 + grp;
        int r_hi = r_lo + 8;
        #pragma unroll
        for (int nt = 0; nt < 4; nt++) {
            int col = wn0 + nt * 8 + tig * 2;
            if (r_lo < M)
                *(float2*)(Cout + r_lo * 128 + col) = make_float2(acc[mt][nt][0], acc[mt][nt][1]);
            if (r_hi < M)
                *(float2*)(Cout + r_hi * 128 + col) = make_float2(acc[mt][nt][2], acc[mt][nt][3]);
        }
    }
}

// ---------------- GEMV: alpha_src / alpha_dst per node ----------------
__global__ __launch_bounds__(256) void gemv_kernel(const float* __restrict__ X, int layer, int M) {
    int gt = blockIdx.x * blockDim.x + threadIdx.x;
    int n = gt >> 5;
    int lane = threadIdx.x & 31;
    if (n >= M) return;
    const float* was = (layer == 1) ? g_was1 : g_was2;
    const float* wad = (layer == 1) ? g_wad1 : g_wad2;
    float4 xv = *(const float4*)(X + n * 128 + lane * 4);
    float4 ws = *(const float4*)(was + lane * 4);
    float4 wd = *(const float4*)(wad + lane * 4);
    float s = xv.x * ws.x + xv.y * ws.y + xv.z * ws.z + xv.w * ws.w;
    float d = xv.x * wd.x + xv.y * wd.y + xv.z * wd.z + xv.w * wd.w;
    #pragma unroll
    for (int o = 16; o; o >>= 1) {
        s += __shfl_xor_sync(0xFFFFFFFFu, s, o);
        d += __shfl_xor_sync(0xFFFFFFFFu, d, o);
    }
    if (lane == 0) { g_as[n] = s; g_ad[n] = d; }
}

// ---------------- fused attention + aggregation + epilogue (warp/node) ----------------
// out[d] = (sum_e ex_e * h_src[src_e]) / (sum_e ex_e + 1e-16) + b + skip[d] + bl
// ex_e = exp(leaky_relu(as[src_e] + ad[d])); softmax normalization deferred to the end.
__global__ __launch_bounds__(256) void agg_kernel(const float* __restrict__ b,
                                                  const float* __restrict__ bl,
                                                  float* __restrict__ out_ext,
                                                  int relu_to_gh, int M) {
    int d = (blockIdx.x * blockDim.x + threadIdx.x) >> 5;
    int lane = threadIdx.x & 31;
    if (d >= M) return;

    int o0 = g_off[d], o1 = g_off[d + 1];
    float add = g_ad[d];

    float4 acc = make_float4(0.f, 0.f, 0.f, 0.f);
    float Sp = 0.f;

    const float* __restrict__ H = g_hsrc;

    for (int base = o0; base < o1; base += 32) {
        int j = base + lane;
        int s = 0;
        float ex = 0.f;
        if (j < o1) {
            s = g_esrc[j];
            float v = g_as[s] + add;
            v = v > 0.f ? v : 0.2f * v;   // LeakyReLU(0.2)
            ex = __expf(v);
        }
        Sp += ex;

        int cnt = min(32, o1 - base);
        int t = 0;
        for (; t + 4 <= cnt; t += 4) {
            float e0 = __shfl_sync(0xFFFFFFFFu, ex, t + 0);
            float e1 = __shfl_sync(0xFFFFFFFFu, ex, t + 1);
            float e2 = __shfl_sync(0xFFFFFFFFu, ex, t + 2);
            float e3 = __shfl_sync(0xFFFFFFFFu, ex, t + 3);
            int s0 = __shfl_sync(0xFFFFFFFFu, s, t + 0);
            int s1 = __shfl_sync(0xFFFFFFFFu, s, t + 1);
            int s2 = __shfl_sync(0xFFFFFFFFu, s, t + 2);
            int s3 = __shfl_sync(0xFFFFFFFFu, s, t + 3);
            float4 v0 = *(const float4*)(H + (long long)s0 * 128 + lane * 4);
            float4 v1 = *(const float4*)(H + (long long)s1 * 128 + lane * 4);
            float4 v2 = *(const float4*)(H + (long long)s2 * 128 + lane * 4);
            float4 v3 = *(const float4*)(H + (long long)s3 * 128 + lane * 4);
            acc.x += e0 * v0.x + e1 * v1.x + e2 * v2.x + e3 * v3.x;
            acc.y += e0 * v0.y + e1 * v1.y + e2 * v2.y + e3 * v3.y;
            acc.z += e0 * v0.z + e1 * v1.z + e2 * v2.z + e3 * v3.z;
            acc.w += e0 * v0.w + e1 * v1.w + e2 * v2.w + e3 * v3.w;
        }
        for (; t < cnt; t++) {
            float et = __shfl_sync(0xFFFFFFFFu, ex, t);
            int   st = __shfl_sync(0xFFFFFFFFu, s, t);
            float4 v = *(const float4*)(H + (long long)st * 128 + lane * 4);
            acc.x += et * v.x; acc.y += et * v.y;
            acc.z += et * v.z; acc.w += et * v.w;
        }
    }

    #pragma unroll
    for (int o = 16; o; o >>= 1) Sp += __shfl_xor_sync(0xFFFFFFFFu, Sp, o);
    float inv = 1.f / (Sp + 1e-16f);

    float4 sk  = *(const float4*)(g_skip + (long long)d * 128 + lane * 4);
    float4 bb  = *(const float4*)(b + lane * 4);
    float4 bb2 = *(const float4*)(bl + lane * 4);

    float4 o;
    o.x = acc.x * inv + bb.x + sk.x + bb2.x;
    o.y = acc.y * inv + bb.y + sk.y + bb2.y;
    o.z = acc.z * inv + bb.z + sk.z + bb2.z;
    o.w = acc.w * inv + bb.w + sk.w + bb2.w;

    if (relu_to_gh) {
        o.x = fmaxf(o.x, 0.f); o.y = fmaxf(o.y, 0.f);
        o.z = fmaxf(o.z, 0.f); o.w = fmaxf(o.w, 0.f);
        *(float4*)(g_h + (long long)d * 128 + lane * 4) = o;
    } else {
        *(float4*)(out_ext + (long long)d * 128 + lane * 4) = o;
    }
}

// ---------------- launch ----------------
extern "C" void kernel_launch(void* const* d_in, const int* in_sizes, int n_in,
                              void* d_out, int out_size) {
    const float* x   = (const float*)d_in[0];
    const int*   ei  = (const int*)  d_in[1];
    const float* W1s = (const float*)d_in[2];
    const float* W1d = (const float*)d_in[3];
    const float* a1s = (const float*)d_in[4];
    const float* a1d = (const float*)d_in[5];
    const float* b1  = (const float*)d_in[6];
    const float* Wl1 = (const float*)d_in[7];
    const float* bl1 = (const float*)d_in[8];
    const float* W2s = (const float*)d_in[9];
    const float* W2d = (const float*)d_in[10];
    const float* a2s = (const float*)d_in[11];
    const float* a2d = (const float*)d_in[12];
    const float* b2  = (const float*)d_in[13];
    const float* Wl2 = (const float*)d_in[14];
    const float* bl2 = (const float*)d_in[15];

    const int M = in_sizes[0] / CC;        // 50000
    const int E = in_sizes[1] / 2;         // 640000
    const int* src = ei;
    const int* dst = ei + E;

    float* p_h = nullptr;
    cudaGetSymbolAddress((void**)&p_h, g_h);  // query only, capture-safe

    static bool attr_set = false;
    if (!attr_set) {
        cudaFuncSetAttribute(sgemm_tf32_kernel,
                             cudaFuncAttributeMaxDynamicSharedMemorySize, SMEM_BYTES);
        attr_set = true;
    }

    const int nodeBlocks  = (M + 255) / 256;
    const int edgeBlocks  = (E + 255) / 256;
    const int warpBlocks  = (int)(((long long)M * 32 + 255) / 256);
    const int scanBlocks  = (M + SCAN_B - 1) / SCAN_B;
    const dim3 gemmGrid((M + 127) / 128, 2);

    combo_kernel<<<1, 128>>>(W1s, a1s, W1d, a1d, W2s, a2s, W2d, a2d);

    // ---- CSR build (once; shared by both layers) ----
    zero_deg_kernel<<<nodeBlocks, 256>>>(M);
    hist_kernel<<<edgeBlocks, 256>>>(dst, E);
    scan1_kernel<<<scanBlocks, SCAN_B>>>(M);
    scan2_kernel<<<1, 128>>>(scanBlocks);
    scan3_kernel<<<nodeBlocks, 256>>>(M, E);
    scatter_kernel<<<edgeBlocks, 256>>>(src, dst, E);

    // ---- layer 1 ----
    sgemm_tf32_kernel<<<gemmGrid, 256, SMEM_BYTES>>>(x, W1s, Wl1, M);
    gemv_kernel<<<warpBlocks, 256>>>(x, 1, M);
    agg_kernel<<<warpBlocks, 256>>>(b1, bl1, nullptr, 1, M);

    // ---- layer 2 ----
    sgemm_tf32_kernel<<<gemmGrid, 256, SMEM_BYTES>>>(p_h, W2s, Wl2, M);
    gemv_kernel<<<warpBlocks, 256>>>(p_h, 2, M);
    agg_kernel<<<warpBlocks, 256>>>(b2, bl2, (float*)d_out, 0, M);
}

// round 4
// speedup vs baseline: 2.3209x; 1.0765x over previous
#include <cuda_runtime.h>
#include <cuda_fp16.h>
#include <cstdint>

#define NN 50000
#define EE 640000
#define CC 128
#define SCAN_B 512

// ---------------- device scratch (no allocations allowed) ----------------
__device__ __half   g_hsrc[NN * CC];   // h_src = in @ Ws   (fp16 gather table)
__device__ float    g_skip[NN * CC];   // skip  = in @ Wl   (fp32)
__device__ float    g_h   [NN * CC];   // layer-1 output
__device__ float    g_as  [NN];        // alpha_src per node
__device__ float    g_ad  [NN];        // alpha_dst per node
__device__ float    g_was1[CC], g_wad1[CC], g_was2[CC], g_wad2[CC];
// CSR (built once per launch; shared by both layers)
__device__ int      g_deg [NN];
__device__ int      g_off [NN + 1];
__device__ int      g_cur [NN];
__device__ int      g_bsum[128];
__device__ int      g_esrc[EE];        // src ids sorted by dst

// ---------------- combo (W@a vectors) + zero_deg merged ----------------
__global__ void combo_zero_kernel(const float* __restrict__ W1s, const float* __restrict__ a1s,
                                  const float* __restrict__ W1d, const float* __restrict__ a1d,
                                  const float* __restrict__ W2s, const float* __restrict__ a2s,
                                  const float* __restrict__ W2d, const float* __restrict__ a2d,
                                  int M) {
    int i = blockIdx.x * blockDim.x + threadIdx.x;
    if (i < M) g_deg[i] = 0;
    if (blockIdx.x == 0 && threadIdx.x < 128) {
        int k = threadIdx.x;
        float s1 = 0.f, d1 = 0.f, s2 = 0.f, d2 = 0.f;
        #pragma unroll 8
        for (int c = 0; c < CC; c++) {
            s1 += W1s[k * CC + c] * a1s[c];
            d1 += W1d[k * CC + c] * a1d[c];
            s2 += W2s[k * CC + c] * a2s[c];
            d2 += W2d[k * CC + c] * a2d[c];
        }
        g_was1[k] = s1; g_wad1[k] = d1; g_was2[k] = s2; g_wad2[k] = d2;
    }
}

// ---------------- CSR build ----------------
__global__ void hist_kernel(const int* __restrict__ dst, int E) {
    int e = blockIdx.x * blockDim.x + threadIdx.x;
    if (e < E) atomicAdd(&g_deg[dst[e]], 1);
}
__global__ __launch_bounds__(SCAN_B) void scan1_kernel(int M) {
    __shared__ int wsum[16];
    int tid = threadIdx.x, lane = tid & 31, wid = tid >> 5;
    int i = blockIdx.x * SCAN_B + tid;
    int v = (i < M) ? g_deg[i] : 0;
    int x = v;
    #pragma unroll
    for (int o = 1; o < 32; o <<= 1) {
        int t = __shfl_up_sync(0xFFFFFFFFu, x, o);
        if (lane >= o) x += t;
    }
    if (lane == 31) wsum[wid] = x;
    __syncthreads();
    if (wid == 0) {
        int s = (lane < 16) ? wsum[lane] : 0;
        #pragma unroll
        for (int o = 1; o < 16; o <<= 1) {
            int t = __shfl_up_sync(0xFFFFFFFFu, s, o);
            if (lane >= o) s += t;
        }
        if (lane < 16) wsum[lane] = s;
    }
    __syncthreads();
    int base = wid ? wsum[wid - 1] : 0;
    int incl = base + x;
    if (i < M) g_off[i] = incl - v;                 // local exclusive
    if (tid == SCAN_B - 1) g_bsum[blockIdx.x] = incl;
}
__global__ __launch_bounds__(128) void scan2_kernel(int B) {
    __shared__ int sm[128];
    int v = (threadIdx.x < B) ? g_bsum[threadIdx.x] : 0;
    sm[threadIdx.x] = v;
    __syncthreads();
    for (int o = 1; o < 128; o <<= 1) {
        int t = (threadIdx.x >= o) ? sm[threadIdx.x - o] : 0;
        __syncthreads();
        sm[threadIdx.x] += t;
        __syncthreads();
    }
    if (threadIdx.x < B) g_bsum[threadIdx.x] = sm[threadIdx.x] - v;  // exclusive
}
__global__ void scan3_kernel(int M, int E) {
    int i = blockIdx.x * blockDim.x + threadIdx.x;
    if (i < M) {
        int o = g_off[i] + g_bsum[i / SCAN_B];
        g_off[i] = o;
        g_cur[i] = o;
    }
    if (i == 0) g_off[M] = E;
}
__global__ void scatter_kernel(const int* __restrict__ src, const int* __restrict__ dst, int E) {
    int e = blockIdx.x * blockDim.x + threadIdx.x;
    if (e >= E) return;
    int pos = atomicAdd(&g_cur[dst[e]], 1);
    g_esrc[pos] = src[e];
}

// ---------------- tf32 tensor-core SGEMM + fused alpha GEMV ----------------
// y==0: Cout = A@B0 -> g_hsrc (fp16), plus g_as/g_ad = (tf32 A)@was/wad
// y==1: Cout = A@B1 -> g_skip (fp32)
#define AS_STRIDE 132
#define BS_STRIDE 136
#define SMEM_BYTES ((128 * AS_STRIDE + 128 * BS_STRIDE) * 4)

__device__ __forceinline__ uint32_t f2tf32(float f) {
    uint32_t r;
    asm("cvt.rna.tf32.f32 %0, %1;" : "=r"(r) : "f"(f));
    return r;
}

__global__ __launch_bounds__(256) void sgemm_tf32_kernel(const float* __restrict__ A,
                                                         const float* __restrict__ B0,
                                                         const float* __restrict__ B1,
                                                         const float* __restrict__ was,
                                                         const float* __restrict__ wad,
                                                         int M) {
    extern __shared__ uint32_t sm[];
    uint32_t* As = sm;
    uint32_t* Bs = sm + 128 * AS_STRIDE;

    const float* B = (blockIdx.y == 0) ? B0 : B1;

    const int tid  = threadIdx.x;
    const int row0 = blockIdx.x * 128;

    #pragma unroll
    for (int i = 0; i < 16; i++) {
        int idx = tid + 256 * i;
        int row = idx >> 5;
        int c4  = (idx & 31) << 2;
        int gr  = row0 + row;
        float4 av = make_float4(0.f, 0.f, 0.f, 0.f);
        if (gr < M) av = *(const float4*)(A + gr * 128 + c4);
        uint32_t* p = As + row * AS_STRIDE + c4;
        p[0] = f2tf32(av.x); p[1] = f2tf32(av.y);
        p[2] = f2tf32(av.z); p[3] = f2tf32(av.w);

        float4 bv = *(const float4*)(B + row * 128 + c4);
        uint32_t* q = Bs + row * BS_STRIDE + c4;
        q[0] = f2tf32(bv.x); q[1] = f2tf32(bv.y);
        q[2] = f2tf32(bv.z); q[3] = f2tf32(bv.w);
    }
    __syncthreads();

    const int w      = tid >> 5;
    const int lane   = tid & 31;
    const int warp_m = w >> 2;
    const int warp_n = w & 3;
    const int wr0    = warp_m * 64;
    const int wn0    = warp_n * 32;
    const int grp    = lane >> 2;
    const int tig    = lane & 3;

    float acc[4][4][4];
    #pragma unroll
    for (int mt = 0; mt < 4; mt++)
        #pragma unroll
        for (int nt = 0; nt < 4; nt++)
            #pragma unroll
            for (int r = 0; r < 4; r++) acc[mt][nt][r] = 0.f;

    #pragma unroll
    for (int k0 = 0; k0 < 128; k0 += 8) {
        uint32_t a[4][4];
        #pragma unroll
        for (int mt = 0; mt < 4; mt++) {
            int r = wr0 + mt * 16 + grp;
            const uint32_t* p = As + r * AS_STRIDE + k0 + tig;
            a[mt][0] = p[0];
            a[mt][1] = p[8 * AS_STRIDE];
            a[mt][2] = p[4];
            a[mt][3] = p[8 * AS_STRIDE + 4];
        }
        uint32_t b[4][2];
        #pragma unroll
        for (int nt = 0; nt < 4; nt++) {
            int c = wn0 + nt * 8 + grp;
            const uint32_t* p = Bs + (k0 + tig) * BS_STRIDE + c;
            b[nt][0] = p[0];
            b[nt][1] = p[4 * BS_STRIDE];
        }
        #pragma unroll
        for (int mt = 0; mt < 4; mt++)
            #pragma unroll
            for (int nt = 0; nt < 4; nt++) {
                float* d = acc[mt][nt];
                asm volatile(
                    "mma.sync.aligned.m16n8k8.row.col.f32.tf32.tf32.f32 "
                    "{%0,%1,%2,%3}, {%4,%5,%6,%7}, {%8,%9}, {%0,%1,%2,%3};"
                    : "+f"(d[0]), "+f"(d[1]), "+f"(d[2]), "+f"(d[3])
                    : "r"(a[mt][0]), "r"(a[mt][1]), "r"(a[mt][2]), "r"(a[mt][3]),
                      "r"(b[nt][0]), "r"(b[nt][1]));
            }
    }

    if (blockIdx.y == 0) {
        // ---- fused alpha GEMV from the resident tf32 A tile ----
        float4 wsv = *(const float4*)(was + lane * 4);
        float4 wdv = *(const float4*)(wad + lane * 4);
        #pragma unroll
        for (int i = 0; i < 16; i++) {
            int r = w * 16 + i;
            uint4 xu = *(const uint4*)(As + r * AS_STRIDE + lane * 4);
            float4 xv = make_float4(__uint_as_float(xu.x), __uint_as_float(xu.y),
                                    __uint_as_float(xu.z), __uint_as_float(xu.w));
            float s  = xv.x * wsv.x + xv.y * wsv.y + xv.z * wsv.z + xv.w * wsv.w;
            float dd = xv.x * wdv.x + xv.y * wdv.y + xv.z * wdv.z + xv.w * wdv.w;
            #pragma unroll
            for (int o = 16; o; o >>= 1) {
                s  += __shfl_xor_sync(0xFFFFFFFFu, s, o);
                dd += __shfl_xor_sync(0xFFFFFFFFu, dd, o);
            }
            if (lane == 0 && row0 + r < M) { g_as[row0 + r] = s; g_ad[row0 + r] = dd; }
        }
        // ---- fp16 epilogue -> g_hsrc ----
        #pragma unroll
        for (int mt = 0; mt < 4; mt++) {
            int r_lo = row0 + wr0 + mt * 16 + grp;
            int r_hi = r_lo + 8;
            #pragma unroll
            for (int nt = 0; nt < 4; nt++) {
                int col = wn0 + nt * 8 + tig * 2;
                if (r_lo < M)
                    *(__half2*)(g_hsrc + (size_t)r_lo * 128 + col) =
                        __float22half2_rn(make_float2(acc[mt][nt][0], acc[mt][nt][1]));
                if (r_hi < M)
                    *(__half2*)(g_hsrc + (size_t)r_hi * 128 + col) =
                        __float22half2_rn(make_float2(acc[mt][nt][2], acc[mt][nt][3]));
            }
        }
    } else {
        #pragma unroll
        for (int mt = 0; mt < 4; mt++) {
            int r_lo = row0 + wr0 + mt * 16 + grp;
            int r_hi = r_lo + 8;
            #pragma unroll
            for (int nt = 0; nt < 4; nt++) {
                int col = wn0 + nt * 8 + tig * 2;
                if (r_lo < M)
                    *(float2*)(g_skip + (size_t)r_lo * 128 + col) =
                        make_float2(acc[mt][nt][0], acc[mt][nt][1]);
                if (r_hi < M)
                    *(float2*)(g_skip + (size_t)r_hi * 128 + col) =
                        make_float2(acc[mt][nt][2], acc[mt][nt][3]);
            }
        }
    }
}

// ---------------- fused attention + aggregation + epilogue (warp/node) ----------------
__global__ __launch_bounds__(256) void agg_kernel(const float* __restrict__ b,
                                                  const float* __restrict__ bl,
                                                  float* __restrict__ out_ext,
                                                  int relu_to_gh, int M) {
    int d = (blockIdx.x * blockDim.x + threadIdx.x) >> 5;
    int lane = threadIdx.x & 31;
    if (d >= M) return;

    int o0 = g_off[d], o1 = g_off[d + 1];
    float add = g_ad[d];

    float4 acc = make_float4(0.f, 0.f, 0.f, 0.f);
    float Sp = 0.f;

    const __half* __restrict__ H = g_hsrc;

    for (int base = o0; base < o1; base += 32) {
        int j = base + lane;
        int s = 0;
        float ex = 0.f;
        if (j < o1) {
            s = g_esrc[j];
            float v = g_as[s] + add;
            v = v > 0.f ? v : 0.2f * v;   // LeakyReLU(0.2)
            ex = __expf(v);
        }
        Sp += ex;

        int cnt = min(32, o1 - base);
        int t = 0;
        for (; t + 4 <= cnt; t += 4) {
            float e0 = __shfl_sync(0xFFFFFFFFu, ex, t + 0);
            float e1 = __shfl_sync(0xFFFFFFFFu, ex, t + 1);
            float e2 = __shfl_sync(0xFFFFFFFFu, ex, t + 2);
            float e3 = __shfl_sync(0xFFFFFFFFu, ex, t + 3);
            int s0 = __shfl_sync(0xFFFFFFFFu, s, t + 0);
            int s1 = __shfl_sync(0xFFFFFFFFu, s, t + 1);
            int s2 = __shfl_sync(0xFFFFFFFFu, s, t + 2);
            int s3 = __shfl_sync(0xFFFFFFFFu, s, t + 3);
            uint2 u0 = *(const uint2*)(H + (size_t)s0 * 128 + lane * 4);
            uint2 u1 = *(const uint2*)(H + (size_t)s1 * 128 + lane * 4);
            uint2 u2 = *(const uint2*)(H + (size_t)s2 * 128 + lane * 4);
            uint2 u3 = *(const uint2*)(H + (size_t)s3 * 128 + lane * 4);
            float2 a0 = __half22float2(*(__half2*)&u0.x), b0 = __half22float2(*(__half2*)&u0.y);
            float2 a1 = __half22float2(*(__half2*)&u1.x), b1 = __half22float2(*(__half2*)&u1.y);
            float2 a2 = __half22float2(*(__half2*)&u2.x), b2 = __half22float2(*(__half2*)&u2.y);
            float2 a3 = __half22float2(*(__half2*)&u3.x), b3 = __half22float2(*(__half2*)&u3.y);
            acc.x += e0 * a0.x + e1 * a1.x + e2 * a2.x + e3 * a3.x;
            acc.y += e0 * a0.y + e1 * a1.y + e2 * a2.y + e3 * a3.y;
            acc.z += e0 * b0.x + e1 * b1.x + e2 * b2.x + e3 * b3.x;
            acc.w += e0 * b0.y + e1 * b1.y + e2 * b2.y + e3 * b3.y;
        }
        for (; t < cnt; t++) {
            float et = __shfl_sync(0xFFFFFFFFu, ex, t);
            int   st = __shfl_sync(0xFFFFFFFFu, s, t);
            uint2 u = *(const uint2*)(H + (size_t)st * 128 + lane * 4);
            float2 fa = __half22float2(*(__half2*)&u.x);
            float2 fb = __half22float2(*(__half2*)&u.y);
            acc.x += et * fa.x; acc.y += et * fa.y;
            acc.z += et * fb.x; acc.w += et * fb.y;
        }
    }

    #pragma unroll
    for (int o = 16; o; o >>= 1) Sp += __shfl_xor_sync(0xFFFFFFFFu, Sp, o);
    float inv = 1.f / (Sp + 1e-16f);

    float4 sk  = *(const float4*)(g_skip + (size_t)d * 128 + lane * 4);
    float4 bb  = *(const float4*)(b + lane * 4);
    float4 bb2 = *(const float4*)(bl + lane * 4);

    float4 o;
    o.x = acc.x * inv + bb.x + sk.x + bb2.x;
    o.y = acc.y * inv + bb.y + sk.y + bb2.y;
    o.z = acc.z * inv + bb.z + sk.z + bb2.z;
    o.w = acc.w * inv + bb.w + sk.w + bb2.w;

    if (relu_to_gh) {
        o.x = fmaxf(o.x, 0.f); o.y = fmaxf(o.y, 0.f);
        o.z = fmaxf(o.z, 0.f); o.w = fmaxf(o.w, 0.f);
        *(float4*)(g_h + (size_t)d * 128 + lane * 4) = o;
    } else {
        *(float4*)(out_ext + (size_t)d * 128 + lane * 4) = o;
    }
}

// ---------------- launch ----------------
extern "C" void kernel_launch(void* const* d_in, const int* in_sizes, int n_in,
                              void* d_out, int out_size) {
    const float* x   = (const float*)d_in[0];
    const int*   ei  = (const int*)  d_in[1];
    const float* W1s = (const float*)d_in[2];
    const float* W1d = (const float*)d_in[3];
    const float* a1s = (const float*)d_in[4];
    const float* a1d = (const float*)d_in[5];
    const float* b1  = (const float*)d_in[6];
    const float* Wl1 = (const float*)d_in[7];
    const float* bl1 = (const float*)d_in[8];
    const float* W2s = (const float*)d_in[9];
    const float* W2d = (const float*)d_in[10];
    const float* a2s = (const float*)d_in[11];
    const float* a2d = (const float*)d_in[12];
    const float* b2  = (const float*)d_in[13];
    const float* Wl2 = (const float*)d_in[14];
    const float* bl2 = (const float*)d_in[15];

    const int M = in_sizes[0] / CC;        // 50000
    const int E = in_sizes[1] / 2;         // 640000
    const int* src = ei;
    const int* dst = ei + E;

    float *p_h = nullptr, *p_was1 = nullptr, *p_wad1 = nullptr,
          *p_was2 = nullptr, *p_wad2 = nullptr;
    cudaGetSymbolAddress((void**)&p_h,    g_h);     // queries only, capture-safe
    cudaGetSymbolAddress((void**)&p_was1, g_was1);
    cudaGetSymbolAddress((void**)&p_wad1, g_wad1);
    cudaGetSymbolAddress((void**)&p_was2, g_was2);
    cudaGetSymbolAddress((void**)&p_wad2, g_wad2);

    static bool attr_set = false;
    if (!attr_set) {
        cudaFuncSetAttribute(sgemm_tf32_kernel,
                             cudaFuncAttributeMaxDynamicSharedMemorySize, SMEM_BYTES);
        attr_set = true;
    }

    const int nodeBlocks  = (M + 255) / 256;
    const int edgeBlocks  = (E + 255) / 256;
    const int warpBlocks  = (int)(((long long)M * 32 + 255) / 256);
    const int scanBlocks  = (M + SCAN_B - 1) / SCAN_B;
    const dim3 gemmGrid((M + 127) / 128, 2);

    // ---- CSR build (once; shared by both layers) + combo ----
    combo_zero_kernel<<<nodeBlocks, 256>>>(W1s, a1s, W1d, a1d, W2s, a2s, W2d, a2d, M);
    hist_kernel<<<edgeBlocks, 256>>>(dst, E);
    scan1_kernel<<<scanBlocks, SCAN_B>>>(M);
    scan2_kernel<<<1, 128>>>(scanBlocks);
    scan3_kernel<<<nodeBlocks, 256>>>(M, E);
    scatter_kernel<<<edgeBlocks, 256>>>(src, dst, E);

    // ---- layer 1 ----
    sgemm_tf32_kernel<<<gemmGrid, 256, SMEM_BYTES>>>(x, W1s, Wl1, p_was1, p_wad1, M);
    agg_kernel<<<warpBlocks, 256>>>(b1, bl1, nullptr, 1, M);

    // ---- layer 2 ----
    sgemm_tf32_kernel<<<gemmGrid, 256, SMEM_BYTES>>>(p_h, W2s, Wl2, p_was2, p_wad2, M);
    agg_kernel<<<warpBlocks, 256>>>(b2, bl2, (float*)d_out, 0, M);
}

// round 5
// speedup vs baseline: 2.4492x; 1.0553x over previous
#include <cuda_runtime.h>
#include <cuda_fp16.h>
#include <cstdint>

#define NN 50000
#define EE 640000
#define CC 128
#define SCAN_B 512

// ---------------- device scratch (no allocations allowed) ----------------
__device__ __half   g_hsrc[NN * CC];   // h_src = in @ Ws   (fp16 gather table)
__device__ float    g_skip[NN * CC];   // skip  = in @ Wl   (fp32)
__device__ float    g_h   [NN * CC];   // layer-1 output
__device__ float    g_as  [NN];        // alpha_src per node
__device__ float    g_ad  [NN];        // alpha_dst per node
__device__ float    g_was1[CC], g_wad1[CC], g_was2[CC], g_wad2[CC];
// CSR (built once per launch; shared by both layers)
__device__ int      g_deg [NN];
__device__ int      g_off [NN + 1];
__device__ int      g_cur [NN];
__device__ int      g_bsum[128];
__device__ int      g_esrc[EE];        // src ids sorted by dst
__device__ int      g_edst[EE];        // dst ids in same order
__device__ float    g_ex  [EE];        // per-edge exp(logit), CSR order

// ---------------- combo (W@a vectors) + zero_deg merged ----------------
__global__ void combo_zero_kernel(const float* __restrict__ W1s, const float* __restrict__ a1s,
                                  const float* __restrict__ W1d, const float* __restrict__ a1d,
                                  const float* __restrict__ W2s, const float* __restrict__ a2s,
                                  const float* __restrict__ W2d, const float* __restrict__ a2d,
                                  int M) {
    int i = blockIdx.x * blockDim.x + threadIdx.x;
    if (i < M) g_deg[i] = 0;
    if (blockIdx.x == 0 && threadIdx.x < 128) {
        int k = threadIdx.x;
        float s1 = 0.f, d1 = 0.f, s2 = 0.f, d2 = 0.f;
        #pragma unroll 8
        for (int c = 0; c < CC; c++) {
            s1 += W1s[k * CC + c] * a1s[c];
            d1 += W1d[k * CC + c] * a1d[c];
            s2 += W2s[k * CC + c] * a2s[c];
            d2 += W2d[k * CC + c] * a2d[c];
        }
        g_was1[k] = s1; g_wad1[k] = d1; g_was2[k] = s2; g_wad2[k] = d2;
    }
}

// ---------------- CSR build ----------------
__global__ void hist_kernel(const int* __restrict__ dst, int E) {
    int e = blockIdx.x * blockDim.x + threadIdx.x;
    if (e < E) atomicAdd(&g_deg[dst[e]], 1);
}
__global__ __launch_bounds__(SCAN_B) void scan1_kernel(int M) {
    __shared__ int wsum[16];
    int tid = threadIdx.x, lane = tid & 31, wid = tid >> 5;
    int i = blockIdx.x * SCAN_B + tid;
    int v = (i < M) ? g_deg[i] : 0;
    int x = v;
    #pragma unroll
    for (int o = 1; o < 32; o <<= 1) {
        int t = __shfl_up_sync(0xFFFFFFFFu, x, o);
        if (lane >= o) x += t;
    }
    if (lane == 31) wsum[wid] = x;
    __syncthreads();
    if (wid == 0) {
        int s = (lane < 16) ? wsum[lane] : 0;
        #pragma unroll
        for (int o = 1; o < 16; o <<= 1) {
            int t = __shfl_up_sync(0xFFFFFFFFu, s, o);
            if (lane >= o) s += t;
        }
        if (lane < 16) wsum[lane] = s;
    }
    __syncthreads();
    int base = wid ? wsum[wid - 1] : 0;
    int incl = base + x;
    if (i < M) g_off[i] = incl - v;                 // local exclusive
    if (tid == SCAN_B - 1) g_bsum[blockIdx.x] = incl;
}
__global__ __launch_bounds__(128) void scan2_kernel(int B) {
    __shared__ int sm[128];
    int v = (threadIdx.x < B) ? g_bsum[threadIdx.x] : 0;
    sm[threadIdx.x] = v;
    __syncthreads();
    for (int o = 1; o < 128; o <<= 1) {
        int t = (threadIdx.x >= o) ? sm[threadIdx.x - o] : 0;
        __syncthreads();
        sm[threadIdx.x] += t;
        __syncthreads();
    }
    if (threadIdx.x < B) g_bsum[threadIdx.x] = sm[threadIdx.x] - v;  // exclusive
}
__global__ void scan3_kernel(int M, int E) {
    int i = blockIdx.x * blockDim.x + threadIdx.x;
    if (i < M) {
        int o = g_off[i] + g_bsum[i / SCAN_B];
        g_off[i] = o;
        g_cur[i] = o;
    }
    if (i == 0) g_off[M] = E;
}
__global__ void scatter_kernel(const int* __restrict__ src, const int* __restrict__ dst, int E) {
    int e = blockIdx.x * blockDim.x + threadIdx.x;
    if (e >= E) return;
    int d = dst[e];
    int pos = atomicAdd(&g_cur[d], 1);
    g_esrc[pos] = src[e];
    g_edst[pos] = d;
}

// ---------------- per-edge ex = exp(leaky(as[s]+ad[d])), CSR order ----------------
__global__ __launch_bounds__(256) void exf_kernel(int E) {
    int e = blockIdx.x * blockDim.x + threadIdx.x;
    if (e >= E) return;
    int s = g_esrc[e], d = g_edst[e];
    float v = __ldg(&g_as[s]) + __ldg(&g_ad[d]);
    v = v > 0.f ? v : 0.2f * v;   // LeakyReLU(0.2)
    g_ex[e] = __expf(v);
}

// ---------------- tf32 tensor-core SGEMM + fused alpha GEMV ----------------
#define AS_STRIDE 132
#define BS_STRIDE 136
#define SMEM_BYTES ((128 * AS_STRIDE + 128 * BS_STRIDE) * 4)

__device__ __forceinline__ uint32_t f2tf32(float f) {
    uint32_t r;
    asm("cvt.rna.tf32.f32 %0, %1;" : "=r"(r) : "f"(f));
    return r;
}

__global__ __launch_bounds__(256) void sgemm_tf32_kernel(const float* __restrict__ A,
                                                         const float* __restrict__ B0,
                                                         const float* __restrict__ B1,
                                                         const float* __restrict__ was,
                                                         const float* __restrict__ wad,
                                                         int M) {
    extern __shared__ uint32_t sm[];
    uint32_t* As = sm;
    uint32_t* Bs = sm + 128 * AS_STRIDE;

    const float* B = (blockIdx.y == 0) ? B0 : B1;

    const int tid  = threadIdx.x;
    const int row0 = blockIdx.x * 128;

    #pragma unroll
    for (int i = 0; i < 16; i++) {
        int idx = tid + 256 * i;
        int row = idx >> 5;
        int c4  = (idx & 31) << 2;
        int gr  = row0 + row;
        float4 av = make_float4(0.f, 0.f, 0.f, 0.f);
        if (gr < M) av = *(const float4*)(A + gr * 128 + c4);
        uint32_t* p = As + row * AS_STRIDE + c4;
        p[0] = f2tf32(av.x); p[1] = f2tf32(av.y);
        p[2] = f2tf32(av.z); p[3] = f2tf32(av.w);

        float4 bv = *(const float4*)(B + row * 128 + c4);
        uint32_t* q = Bs + row * BS_STRIDE + c4;
        q[0] = f2tf32(bv.x); q[1] = f2tf32(bv.y);
        q[2] = f2tf32(bv.z); q[3] = f2tf32(bv.w);
    }
    __syncthreads();

    const int w      = tid >> 5;
    const int lane   = tid & 31;
    const int warp_m = w >> 2;
    const int warp_n = w & 3;
    const int wr0    = warp_m * 64;
    const int wn0    = warp_n * 32;
    const int grp    = lane >> 2;
    const int tig    = lane & 3;

    float acc[4][4][4];
    #pragma unroll
    for (int mt = 0; mt < 4; mt++)
        #pragma unroll
        for (int nt = 0; nt < 4; nt++)
            #pragma unroll
            for (int r = 0; r < 4; r++) acc[mt][nt][r] = 0.f;

    #pragma unroll
    for (int k0 = 0; k0 < 128; k0 += 8) {
        uint32_t a[4][4];
        #pragma unroll
        for (int mt = 0; mt < 4; mt++) {
            int r = wr0 + mt * 16 + grp;
            const uint32_t* p = As + r * AS_STRIDE + k0 + tig;
            a[mt][0] = p[0];
            a[mt][1] = p[8 * AS_STRIDE];
            a[mt][2] = p[4];
            a[mt][3] = p[8 * AS_STRIDE + 4];
        }
        uint32_t b[4][2];
        #pragma unroll
        for (int nt = 0; nt < 4; nt++) {
            int c = wn0 + nt * 8 + grp;
            const uint32_t* p = Bs + (k0 + tig) * BS_STRIDE + c;
            b[nt][0] = p[0];
            b[nt][1] = p[4 * BS_STRIDE];
        }
        #pragma unroll
        for (int mt = 0; mt < 4; mt++)
            #pragma unroll
            for (int nt = 0; nt < 4; nt++) {
                float* d = acc[mt][nt];
                asm volatile(
                    "mma.sync.aligned.m16n8k8.row.col.f32.tf32.tf32.f32 "
                    "{%0,%1,%2,%3}, {%4,%5,%6,%7}, {%8,%9}, {%0,%1,%2,%3};"
                    : "+f"(d[0]), "+f"(d[1]), "+f"(d[2]), "+f"(d[3])
                    : "r"(a[mt][0]), "r"(a[mt][1]), "r"(a[mt][2]), "r"(a[mt][3]),
                      "r"(b[nt][0]), "r"(b[nt][1]));
            }
    }

    if (blockIdx.y == 0) {
        // ---- fused alpha GEMV from the resident tf32 A tile ----
        float4 wsv = *(const float4*)(was + lane * 4);
        float4 wdv = *(const float4*)(wad + lane * 4);
        #pragma unroll
        for (int i = 0; i < 16; i++) {
            int r = w * 16 + i;
            uint4 xu = *(const uint4*)(As + r * AS_STRIDE + lane * 4);
            float4 xv = make_float4(__uint_as_float(xu.x), __uint_as_float(xu.y),
                                    __uint_as_float(xu.z), __uint_as_float(xu.w));
            float s  = xv.x * wsv.x + xv.y * wsv.y + xv.z * wsv.z + xv.w * wsv.w;
            float dd = xv.x * wdv.x + xv.y * wdv.y + xv.z * wdv.z + xv.w * wdv.w;
            #pragma unroll
            for (int o = 16; o; o >>= 1) {
                s  += __shfl_xor_sync(0xFFFFFFFFu, s, o);
                dd += __shfl_xor_sync(0xFFFFFFFFu, dd, o);
            }
            if (lane == 0 && row0 + r < M) { g_as[row0 + r] = s; g_ad[row0 + r] = dd; }
        }
        // ---- fp16 epilogue -> g_hsrc ----
        #pragma unroll
        for (int mt = 0; mt < 4; mt++) {
            int r_lo = row0 + wr0 + mt * 16 + grp;
            int r_hi = r_lo + 8;
            #pragma unroll
            for (int nt = 0; nt < 4; nt++) {
                int col = wn0 + nt * 8 + tig * 2;
                if (r_lo < M)
                    *(__half2*)(g_hsrc + (size_t)r_lo * 128 + col) =
                        __float22half2_rn(make_float2(acc[mt][nt][0], acc[mt][nt][1]));
                if (r_hi < M)
                    *(__half2*)(g_hsrc + (size_t)r_hi * 128 + col) =
                        __float22half2_rn(make_float2(acc[mt][nt][2], acc[mt][nt][3]));
            }
        }
    } else {
        #pragma unroll
        for (int mt = 0; mt < 4; mt++) {
            int r_lo = row0 + wr0 + mt * 16 + grp;
            int r_hi = r_lo + 8;
            #pragma unroll
            for (int nt = 0; nt < 4; nt++) {
                int col = wn0 + nt * 8 + tig * 2;
                if (r_lo < M)
                    *(float2*)(g_skip + (size_t)r_lo * 128 + col) =
                        make_float2(acc[mt][nt][0], acc[mt][nt][1]);
                if (r_hi < M)
                    *(float2*)(g_skip + (size_t)r_hi * 128 + col) =
                        make_float2(acc[mt][nt][2], acc[mt][nt][3]);
            }
        }
    }
}

// ---------------- fused aggregation + epilogue (warp/node, no shuffles) ----------------
// All lanes read the same g_esrc/g_ex addresses (warp-uniform broadcast loads),
// so every lane holds the full Sp — no final reduce needed.
__global__ __launch_bounds__(256) void agg_kernel(const float* __restrict__ b,
                                                  const float* __restrict__ bl,
                                                  float* __restrict__ out_ext,
                                                  int relu_to_gh, int M) {
    int d = (blockIdx.x * blockDim.x + threadIdx.x) >> 5;
    int lane = threadIdx.x & 31;
    if (d >= M) return;

    int o0 = g_off[d], o1 = g_off[d + 1];

    float4 acc = make_float4(0.f, 0.f, 0.f, 0.f);
    float Sp = 0.f;
    const __half* __restrict__ H = g_hsrc;

    int j = o0;
    for (; j + 8 <= o1; j += 8) {
        int   s_[8];
        float e_[8];
        #pragma unroll
        for (int u = 0; u < 8; u++) {
            s_[u] = __ldg(&g_esrc[j + u]);   // warp-uniform broadcast
            e_[u] = __ldg(&g_ex[j + u]);
        }
        Sp += (e_[0] + e_[1]) + (e_[2] + e_[3]) + (e_[4] + e_[5]) + (e_[6] + e_[7]);
        uint2 u_[8];
        #pragma unroll
        for (int u = 0; u < 8; u++)
            u_[u] = *(const uint2*)(H + (size_t)s_[u] * 128 + lane * 4);
        #pragma unroll
        for (int u = 0; u < 8; u++) {
            float2 fa = __half22float2(*(__half2*)&u_[u].x);
            float2 fb = __half22float2(*(__half2*)&u_[u].y);
            acc.x += e_[u] * fa.x; acc.y += e_[u] * fa.y;
            acc.z += e_[u] * fb.x; acc.w += e_[u] * fb.y;
        }
    }
    for (; j < o1; j++) {
        int   s  = __ldg(&g_esrc[j]);
        float ex = __ldg(&g_ex[j]);
        Sp += ex;
        uint2 u = *(const uint2*)(H + (size_t)s * 128 + lane * 4);
        float2 fa = __half22float2(*(__half2*)&u.x);
        float2 fb = __half22float2(*(__half2*)&u.y);
        acc.x += ex * fa.x; acc.y += ex * fa.y;
        acc.z += ex * fb.x; acc.w += ex * fb.y;
    }

    float inv = 1.f / (Sp + 1e-16f);

    float4 sk  = *(const float4*)(g_skip + (size_t)d * 128 + lane * 4);
    float4 bb  = *(const float4*)(b + lane * 4);
    float4 bb2 = *(const float4*)(bl + lane * 4);

    float4 o;
    o.x = acc.x * inv + bb.x + sk.x + bb2.x;
    o.y = acc.y * inv + bb.y + sk.y + bb2.y;
    o.z = acc.z * inv + bb.z + sk.z + bb2.z;
    o.w = acc.w * inv + bb.w + sk.w + bb2.w;

    if (relu_to_gh) {
        o.x = fmaxf(o.x, 0.f); o.y = fmaxf(o.y, 0.f);
        o.z = fmaxf(o.z, 0.f); o.w = fmaxf(o.w, 0.f);
        *(float4*)(g_h + (size_t)d * 128 + lane * 4) = o;
    } else {
        *(float4*)(out_ext + (size_t)d * 128 + lane * 4) = o;
    }
}

// ---------------- launch ----------------
extern "C" void kernel_launch(void* const* d_in, const int* in_sizes, int n_in,
                              void* d_out, int out_size) {
    const float* x   = (const float*)d_in[0];
    const int*   ei  = (const int*)  d_in[1];
    const float* W1s = (const float*)d_in[2];
    const float* W1d = (const float*)d_in[3];
    const float* a1s = (const float*)d_in[4];
    const float* a1d = (const float*)d_in[5];
    const float* b1  = (const float*)d_in[6];
    const float* Wl1 = (const float*)d_in[7];
    const float* bl1 = (const float*)d_in[8];
    const float* W2s = (const float*)d_in[9];
    const float* W2d = (const float*)d_in[10];
    const float* a2s = (const float*)d_in[11];
    const float* a2d = (const float*)d_in[12];
    const float* b2  = (const float*)d_in[13];
    const float* Wl2 = (const float*)d_in[14];
    const float* bl2 = (const float*)d_in[15];

    const int M = in_sizes[0] / CC;        // 50000
    const int E = in_sizes[1] / 2;         // 640000
    const int* src = ei;
    const int* dst = ei + E;

    float *p_h = nullptr, *p_was1 = nullptr, *p_wad1 = nullptr,
          *p_was2 = nullptr, *p_wad2 = nullptr;
    cudaGetSymbolAddress((void**)&p_h,    g_h);     // queries only, capture-safe
    cudaGetSymbolAddress((void**)&p_was1, g_was1);
    cudaGetSymbolAddress((void**)&p_wad1, g_wad1);
    cudaGetSymbolAddress((void**)&p_was2, g_was2);
    cudaGetSymbolAddress((void**)&p_wad2, g_wad2);

    static bool attr_set = false;
    if (!attr_set) {
        cudaFuncSetAttribute(sgemm_tf32_kernel,
                             cudaFuncAttributeMaxDynamicSharedMemorySize, SMEM_BYTES);
        attr_set = true;
    }

    const int nodeBlocks  = (M + 255) / 256;
    const int edgeBlocks  = (E + 255) / 256;
    const int warpBlocks  = (int)(((long long)M * 32 + 255) / 256);
    const int scanBlocks  = (M + SCAN_B - 1) / SCAN_B;
    const dim3 gemmGrid((M + 127) / 128, 2);

    // launch order arranged so the 4th launch (ncu -s window) is the SGEMM
    combo_zero_kernel<<<nodeBlocks, 256>>>(W1s, a1s, W1d, a1d, W2s, a2s, W2d, a2d, M);  // 1
    hist_kernel<<<edgeBlocks, 256>>>(dst, E);                                           // 2
    scan1_kernel<<<scanBlocks, SCAN_B>>>(M);                                            // 3
    sgemm_tf32_kernel<<<gemmGrid, 256, SMEM_BYTES>>>(x, W1s, Wl1, p_was1, p_wad1, M);   // 4 (layer 1, CSR-independent)
    scan2_kernel<<<1, 128>>>(scanBlocks);                                               // 5
    scan3_kernel<<<nodeBlocks, 256>>>(M, E);                                            // 6
    scatter_kernel<<<edgeBlocks, 256>>>(src, dst, E);                                   // 7

    // ---- layer 1 ----
    exf_kernel<<<edgeBlocks, 256>>>(E);                                                 // 8
    agg_kernel<<<warpBlocks, 256>>>(b1, bl1, nullptr, 1, M);                            // 9

    // ---- layer 2 ----
    sgemm_tf32_kernel<<<gemmGrid, 256, SMEM_BYTES>>>(p_h, W2s, Wl2, p_was2, p_wad2, M); // 10
    exf_kernel<<<edgeBlocks, 256>>>(E);                                                 // 11
    agg_kernel<<<warpBlocks, 256>>>(b2, bl2, (float*)d_out, 0, M);                      // 12
}